// round 17
// baseline (speedup 1.0000x reference)
#include <cuda_runtime.h>
#include <cuda_fp16.h>
#include <math.h>
#include <stdint.h>

#define Bmax 4
#define C_ 64
#define H_ 128
#define W_ 128
#define O_ 64
#define K_ 9
#define HW_ (H_*W_)

__device__ __forceinline__ uint32_t cvt_h2(float hi, float lo) {
    uint32_t r; asm("cvt.rn.f16x2.f32 %0, %1, %2;" : "=r"(r) : "f"(hi), "f"(lo)); return r;
}
__device__ __forceinline__ void mma16(float4 &d, uint32_t a0, uint32_t a1, uint32_t a2, uint32_t a3,
                                      uint32_t b0, uint32_t b1) {
    asm("mma.sync.aligned.m16n8k16.row.col.f32.f16.f16.f32 "
        "{%0,%1,%2,%3},{%4,%5,%6,%7},{%8,%9},{%0,%1,%2,%3};"
        : "+f"(d.x), "+f"(d.y), "+f"(d.z), "+f"(d.w)
        : "r"(a0), "r"(a1), "r"(a2), "r"(a3), "r"(b0), "r"(b1));
}
__device__ __forceinline__ void ldsm4(uint32_t &a0, uint32_t &a1, uint32_t &a2, uint32_t &a3,
                                      uint32_t addr) {
    asm volatile("ldmatrix.sync.aligned.m8n8.x4.shared.b16 {%0,%1,%2,%3}, [%4];"
                 : "=r"(a0), "=r"(a1), "=r"(a2), "=r"(a3) : "r"(addr));
}
__device__ __forceinline__ void cp16(uint32_t dst, const void* src, int sz) {
    asm volatile("cp.async.ca.shared.global [%0], [%1], 16, %2;"
                 :: "r"(dst), "l"(src), "r"(sz) : "memory");
}
#define CP_COMMIT() asm volatile("cp.async.commit_group;" ::: "memory")
#define CP_WAIT0()  asm volatile("cp.async.wait_group 0;" ::: "memory")

// ---------------- device scratch ----------------
__device__ __align__(16) __half g_xh[Bmax*HW_*C_ + 16384];  // NHWC x (fp16), padded
__device__ uint4 g_wt3h4[K_*4*4*32];          // main: [k][ks(4)][j2(4)][lane]
__device__ uint4 g_w1h4[K_*4*2*32];           // om:   [kk(9)][ks(4)][j2(2)][lane]

// ---------------- merged prep: transpose->fp16 NHWC + repack ----------------
#define NT_BLKS 1024
#define NREP4 (K_*4*4*32 + K_*4*2*32)
#define NREP_BLKS ((NREP4 + 255)/256)

__global__ __launch_bounds__(256)
void k_prep(const float* __restrict__ x, const float* __restrict__ wgt,
            const float* __restrict__ omw) {
    int bid = blockIdx.x;
    if (bid < NT_BLKS) {
        __shared__ float t[2][2][32][33];
        int wb = bid & 3;
        int h0 = ((bid >> 2) & 63) * 2;
        int b  = bid >> 8;
        int w0 = wb * 32;
        int tid = threadIdx.x;
        int r  = tid >> 3;
        int q  = tid & 7;
#pragma unroll
        for (int hh = 0; hh < 2; hh++) {
            float4 v0 = *(const float4*)(x + ((size_t)(b*C_ + r     )*H_ + h0 + hh)*W_ + w0 + q*4);
            float4 v1 = *(const float4*)(x + ((size_t)(b*C_ + 32 + r)*H_ + h0 + hh)*W_ + w0 + q*4);
            t[hh][0][r][q*4] = v0.x; t[hh][0][r][q*4+1] = v0.y; t[hh][0][r][q*4+2] = v0.z; t[hh][0][r][q*4+3] = v0.w;
            t[hh][1][r][q*4] = v1.x; t[hh][1][r][q*4+1] = v1.y; t[hh][1][r][q*4+2] = v1.z; t[hh][1][r][q*4+3] = v1.w;
        }
        __syncthreads();
#pragma unroll
        for (int hh = 0; hh < 2; hh++) {
            float4 o0, o1;
            o0.x = t[hh][0][q*4][r]; o0.y = t[hh][0][q*4+1][r]; o0.z = t[hh][0][q*4+2][r]; o0.w = t[hh][0][q*4+3][r];
            o1.x = t[hh][1][q*4][r]; o1.y = t[hh][1][q*4+1][r]; o1.z = t[hh][1][q*4+2][r]; o1.w = t[hh][1][q*4+3][r];
            __half* dst = g_xh + ((size_t)(b*H_ + h0 + hh)*W_ + w0 + r)*C_;
            *(uint2*)(dst + q*4)      = make_uint2(cvt_h2(o0.y, o0.x), cvt_h2(o0.w, o0.z));
            *(uint2*)(dst + 32 + q*4) = make_uint2(cvt_h2(o1.y, o1.x), cvt_h2(o1.w, o1.z));
        }
    } else {
        int f = (bid - NT_BLKS)*256 + threadIdx.x;
        if (f < K_*4*4*32) {              // main weights: [k][ks][j2(2b)][lane(5b)]
            int lane = f & 31;
            int j2 = (f >> 5) & 3;
            int ks = (f >> 7) & 3;
            int k  = f >> 9;
            int c0 = ks*16 + 2*(lane & 3);
            uint4 r;
            {
                int o = (2*j2)*8 + (lane >> 2);
                const float* wb2 = wgt + (size_t)o*C_*K_;
                r.x = cvt_h2(wb2[(c0+1)*K_ + k], wb2[c0*K_ + k]);
                r.y = cvt_h2(wb2[(c0+9)*K_ + k], wb2[(c0+8)*K_ + k]);
            }
            {
                int o = (2*j2+1)*8 + (lane >> 2);
                const float* wb2 = wgt + (size_t)o*C_*K_;
                r.z = cvt_h2(wb2[(c0+1)*K_ + k], wb2[c0*K_ + k]);
                r.w = cvt_h2(wb2[(c0+9)*K_ + k], wb2[(c0+8)*K_ + k]);
            }
            g_wt3h4[f] = r;
        } else if (f < NREP4) {           // om weights: [kk][ks(2b)][j2(1b)][lane(5b)]
            int f2 = f - K_*4*4*32;
            int lane = f2 & 31;
            int j2 = (f2 >> 5) & 1;
            int ks = (f2 >> 6) & 3;
            int kk = f2 >> 8;
            int c0 = ks*16 + 2*(lane & 3);
            uint4 r = make_uint4(0, 0, 0, 0);
            {
                int oc = (2*j2)*8 + (lane >> 2);
                if (oc < 27) {
                    const float* wb2 = omw + (size_t)oc*C_*K_;
                    r.x = cvt_h2(wb2[(c0+1)*K_ + kk], wb2[c0*K_ + kk]);
                    r.y = cvt_h2(wb2[(c0+9)*K_ + kk], wb2[(c0+8)*K_ + kk]);
                }
            }
            {
                int oc = (2*j2+1)*8 + (lane >> 2);
                if (oc < 27) {
                    const float* wb2 = omw + (size_t)oc*C_*K_;
                    r.z = cvt_h2(wb2[(c0+1)*K_ + kk], wb2[c0*K_ + kk]);
                    r.w = cvt_h2(wb2[(c0+9)*K_ + kk], wb2[(c0+8)*K_ + kk]);
                }
            }
            g_w1h4[f2] = r;
        }
    }
}

// ---------------- fused DCN: one block per (b, h) row, 512 threads, pipelined ----------------
#define SM_A0  0        // 18720 B : A tile buf0 (pitch 144B); om_s unions here
#define SM_A1  18720    // 18720 B : A tile buf1
#define SM_B0  37440    // 12288 B : B frag buf0
#define SM_B1  49728    // 12288 B : B frag buf1
#define SM_SW  62016    // 18432 B : float4[9][128] corner weights
#define SM_I0  80448    // 4608  B : int[9][128]
#define SM_DD  85056    // 4608  B : int[9][128]
#define SM_TOT 89664

__global__ __launch_bounds__(512, 2)
void k_dcn(const float* __restrict__ bias, const float* __restrict__ om_bias,
           float* __restrict__ out) {
    extern __shared__ char sm[];
    float*    om_s  = (float*)(sm + SM_A0);
    float4*   s_w   = (float4*)(sm + SM_SW);
    int*      s_i0  = (int*)(sm + SM_I0);
    int*      s_d   = (int*)(sm + SM_DD);

    const int tid  = threadIdx.x;
    const int lane = tid & 31;
    const int wid  = tid >> 5;
    const int m    = wid & 7;
    const int n    = wid >> 3;
    const int tg   = lane >> 2;
    const int tig  = lane & 3;
    const int h    = blockIdx.x;
    const int b    = blockIdx.y;
    const int row0 = m*16 + tg;
    const __half* xh = g_xh + (size_t)b*HW_*C_;

    const uint32_t smb = (uint32_t)__cvta_generic_to_shared(sm);
    const int laneRow  = ((lane >> 3) & 1)*8 + (lane & 7);
    const int chunkOff = (lane >> 4)*16;
    const uint32_t aFragOff = (uint32_t)(m*16 + laneRow)*144 + chunkOff;

    auto bufB4 = [&](int i) { return (uint4*)(sm + (i ? SM_B1 : SM_B0)); };
    auto aBase = [&](int i) { return smb + (i ? SM_A1 : SM_A0) + aFragOff; };

    // ---------- Phase 1: offset/mask conv, cp.async staging, pipelined over ky ----------
    float4 acc1[2];
    acc1[0] = make_float4(0.f, 0.f, 0.f, 0.f);
    acc1[1] = make_float4(0.f, 0.f, 0.f, 0.f);

    auto stageA1 = [&](int ky, int buf) {
        int yy = h + ky - 1;
        bool yok = (yy >= 0 && yy < H_);
        uint32_t dstb = smb + (buf ? SM_A1 : SM_A0);
        for (int e = tid; e < 1040; e += 512) {
            int c8 = e & 7, r = e >> 3;
            int xx = r - 1;
            bool ok = yok && (xx >= 0) && (xx < W_);
            const __half* src = ok ? (xh + ((size_t)yy*W_ + xx)*C_ + c8*8) : xh;
            cp16(dstb + (uint32_t)(r*144 + c8*16), src, ok ? 16 : 0);
        }
    };
    auto stageB1 = [&](int ky, int buf) {
        const char* src = (const char*)(g_w1h4 + (size_t)ky*3*256);
        uint32_t dstb = smb + (buf ? SM_B1 : SM_B0);
        for (int e = tid; e < 768; e += 512)
            cp16(dstb + (uint32_t)e*16, src + (size_t)e*16, 16);
    };

    stageA1(0, 0); stageB1(0, 0); CP_COMMIT(); CP_WAIT0();
    __syncthreads();
    for (int ky = 0; ky < 3; ky++) {
        int cur = ky & 1;
        if (ky < 2) { stageA1(ky + 1, cur ^ 1); stageB1(ky + 1, cur ^ 1); CP_COMMIT(); }
        const uint4* bB = bufB4(cur);
        uint32_t ab = aBase(cur);
#pragma unroll
        for (int ks = 0; ks < 4; ks++) {
#pragma unroll
            for (int kx = 0; kx < 3; kx++) {
                uint32_t a0, a1, a2, a3;
                ldsm4(a0, a1, a2, a3, ab + kx*144 + ks*32);
                uint4 bf = bB[kx*256 + (ks*2 + n)*32 + lane];
                mma16(acc1[0], a0, a1, a2, a3, bf.x, bf.y);
                mma16(acc1[1], a0, a1, a2, a3, bf.z, bf.w);
            }
        }
        if (ky < 2) CP_WAIT0();
        __syncthreads();
    }

    // ---------- Phase 2a: write om fragments (stride 36 floats) into A0 (dead) ----------
#pragma unroll
    for (int jl = 0; jl < 2; jl++) {
        int col = (2*n + jl)*8 + tig*2;
        *(float2*)(om_s + row0*36 + col)     = make_float2(acc1[jl].x, acc1[jl].y);
        *(float2*)(om_s + (row0+8)*36 + col) = make_float2(acc1[jl].z, acc1[jl].w);
    }
    __syncthreads();

    // ---------- Phase 2b: bilinear sampling prep per (px, k) ----------
    for (int e = tid; e < 1152; e += 512) {
        int px = e & 127, k = e >> 7;
        int ky = k / 3, kx = k - 3*ky;
        float oy = om_s[px*36 + k]      + __ldg(om_bias + k);
        float ox = om_s[px*36 + 9 + k]  + __ldg(om_bias + 9 + k);
        float mz = om_s[px*36 + 18 + k] + __ldg(om_bias + 18 + k);
        float mk = 1.f / (1.f + expf(-mz));
        float pyf = oy + (float)(h - 1 + ky);
        float pxf = ox + (float)(px - 1 + kx);
        float y0f = floorf(pyf), x0f = floorf(pxf);
        float ly = pyf - y0f, lx = pxf - x0f;
        int y0 = (int)y0f, x0 = (int)x0f;
        bool vy0 = (y0 >= 0)   & (y0 < H_);
        bool vy1 = (y0 >= -1)  & (y0 < H_-1);
        bool vx0 = (x0 >= 0)   & (x0 < W_);
        bool vx1 = (x0 >= -1)  & (x0 < W_-1);
        float w00 = (1.f-ly)*(1.f-lx)*mk * (float)(vy0 & vx0);
        float w01 = (1.f-ly)*lx*mk       * (float)(vy0 & vx1);
        float w10 = ly*(1.f-lx)*mk       * (float)(vy1 & vx0);
        float w11 = ly*lx*mk             * (float)(vy1 & vx1);
        int cy0 = min(max(y0, 0), H_-1),   cx0 = min(max(x0, 0), W_-1);
        int cy1 = min(max(y0+1, 0), H_-1), cx1 = min(max(x0+1, 0), W_-1);
        s_w[e]  = make_float4(w00, w01, w10, w11);
        s_i0[e] = cy0*W_ + cx0;
        s_d[e]  = (cx1 - cx0) | (((cy1 - cy0)*W_) << 16);
    }
    __syncthreads();

    // ---------- Phase 3: main DCN, register-prefetched gathers ----------
    float4 acc[4];
#pragma unroll
    for (int j = 0; j < 4; j++) acc[j] = make_float4(0.f, 0.f, 0.f, 0.f);

    uint4 ga[8];   // prefetched corners: 2 elems x 4 corners

    auto loadA3 = [&](int k) {
#pragma unroll
        for (int i = 0; i < 2; i++) {
            int e = tid + i*512;
            int c8 = e & 7, px = e >> 3;
            int se = k*128 + px;
            int i0 = s_i0[se];
            int d  = s_d[se];
            int dx  = d & 0xffff;
            int dyw = d >> 16;
            const __half* p00 = xh + (size_t)i0*C_ + c8*8;
            ga[i*4+0] = *(const uint4*)(p00);
            ga[i*4+1] = *(const uint4*)(p00 + dx*C_);
            ga[i*4+2] = *(const uint4*)(p00 + dyw*C_);
            ga[i*4+3] = *(const uint4*)(p00 + (size_t)(dyw+dx)*C_);
        }
    };
    auto combineA3 = [&](int k, int buf) {
        uint4* xs4 = (uint4*)(sm + (buf ? SM_A1 : SM_A0));
#pragma unroll
        for (int i = 0; i < 2; i++) {
            int e = tid + i*512;
            int c8 = e & 7, px = e >> 3;
            float4 wv = s_w[k*128 + px];
            __half2 w00h = __float2half2_rn(wv.x);
            __half2 w01h = __float2half2_rn(wv.y);
            __half2 w10h = __float2half2_rn(wv.z);
            __half2 w11h = __float2half2_rn(wv.w);
            const __half2* Ah = (const __half2*)&ga[i*4+0];
            const __half2* Bh = (const __half2*)&ga[i*4+1];
            const __half2* Ch = (const __half2*)&ga[i*4+2];
            const __half2* Dh = (const __half2*)&ga[i*4+3];
            uint4 r;
            __half2* Rh = (__half2*)&r;
#pragma unroll
            for (int q = 0; q < 4; q++) {
                __half2 t = __hmul2(w00h, Ah[q]);
                t = __hfma2(w01h, Bh[q], t);
                t = __hfma2(w10h, Ch[q], t);
                t = __hfma2(w11h, Dh[q], t);
                Rh[q] = t;
            }
            xs4[px*9 + c8] = r;
        }
    };
    auto stageB3 = [&](int k, int buf) {
        const char* src = (const char*)(g_wt3h4 + (size_t)k*512);
        uint32_t dstb = smb + (buf ? SM_B1 : SM_B0);
        cp16(dstb + (uint32_t)tid*16, src + (size_t)tid*16, 16);
    };

    loadA3(0); stageB3(0, 1); CP_COMMIT();
    combineA3(0, 1);
    CP_WAIT0();
    __syncthreads();
    for (int k = 0; k < K_; k++) {
        int cur = (k & 1) ^ 1;        // k=0 -> buf1
        if (k < K_ - 1) { loadA3(k + 1); stageB3(k + 1, cur ^ 1); CP_COMMIT(); }
        const uint4* bB = bufB4(cur);
        uint32_t ab = aBase(cur);
#pragma unroll
        for (int ks = 0; ks < 4; ks++) {
            uint32_t a0, a1, a2, a3;
            ldsm4(a0, a1, a2, a3, ab + ks*32);
#pragma unroll
            for (int j2l = 0; j2l < 2; j2l++) {
                uint4 bf = bB[(ks*4 + 2*n + j2l)*32 + lane];
                mma16(acc[2*j2l],     a0, a1, a2, a3, bf.x, bf.y);
                mma16(acc[2*j2l + 1], a0, a1, a2, a3, bf.z, bf.w);
            }
        }
        if (k < K_ - 1) { combineA3(k + 1, cur ^ 1); CP_WAIT0(); }
        __syncthreads();
    }

    // ---------- Epilogue: NCHW store + bias ----------
#pragma unroll
    for (int jl = 0; jl < 4; jl++) {
        int o = (4*n + jl)*8 + tig*2;
        float b0v = __ldg(bias + o);
        float b1v = __ldg(bias + o + 1);
        size_t base0 = (((size_t)b*O_ + o    )*H_ + h)*W_;
        size_t base1 = (((size_t)b*O_ + o + 1)*H_ + h)*W_;
        out[base0 + row0]     = acc[jl].x + b0v;
        out[base1 + row0]     = acc[jl].y + b1v;
        out[base0 + row0 + 8] = acc[jl].z + b0v;
        out[base1 + row0 + 8] = acc[jl].w + b1v;
    }
}

extern "C" void kernel_launch(void* const* d_in, const int* in_sizes, int n_in,
                              void* d_out, int out_size) {
    const float* x         = (const float*)d_in[0];
    const float* weight    = (const float*)d_in[1];
    const float* bias      = (const float*)d_in[2];
    const float* om_weight = (const float*)d_in[3];
    const float* om_bias   = (const float*)d_in[4];
    float* out = (float*)d_out;

    int B = in_sizes[0] / (C_*H_*W_);
    if (B < 1) B = 1;
    if (B > Bmax) B = Bmax;

    cudaFuncSetAttribute(k_dcn, cudaFuncAttributeMaxDynamicSharedMemorySize, SM_TOT);

    k_prep<<<NT_BLKS + NREP_BLKS, 256>>>(x, weight, om_weight);
    k_dcn<<<dim3(H_, B), 512, SM_TOT>>>(bias, om_bias, out);
}